// round 1
// baseline (speedup 1.0000x reference)
#include <cuda_runtime.h>
#include <mma.h>
#include <math.h>

using namespace nvcuda;

#define T_TOK 4096
#define HDIM  2048
#define IDIM  4096
#define NEXP  8
#define TOPK  4
#define CAP   4096

// ---------------- scratch (device globals: allocation-free) ----------------
__device__ int   g_counts[NEXP];
__device__ int   g_tok[NEXP * CAP];                 // per-expert token lists
__device__ int   g_slot_epos[T_TOK * TOPK];         // e*CAP+pos per (token,k)
__device__ float g_slot_gate[T_TOK * TOPK];         // renormalized gate
__device__ float g_h1[(size_t)NEXP * CAP * IDIM];   // 536 MB
__device__ float g_h2[(size_t)NEXP * CAP * IDIM];   // 536 MB
__device__ float g_y [(size_t)NEXP * CAP * HDIM];   // 268 MB

// ---------------- init: zero expert counts (graph-replay safe) -------------
__global__ void init_kernel() {
    if (threadIdx.x < NEXP) g_counts[threadIdx.x] = 0;
}

// ---------------- router: 1 warp per token ----------------------------------
__global__ void router_kernel(const float* __restrict__ x,
                              const float* __restrict__ rw) {
    int gtid = blockIdx.x * blockDim.x + threadIdx.x;
    int tok  = gtid >> 5;
    int lane = gtid & 31;
    if (tok >= T_TOK) return;

    const float* xr = x + (size_t)tok * HDIM;
    float acc[NEXP];
#pragma unroll
    for (int e = 0; e < NEXP; e++) acc[e] = 0.f;

    for (int h = lane; h < HDIM; h += 32) {
        float xv = xr[h];
        const float* r = rw + (size_t)h * NEXP;
#pragma unroll
        for (int e = 0; e < NEXP; e++) acc[e] = fmaf(xv, r[e], acc[e]);
    }
#pragma unroll
    for (int off = 16; off; off >>= 1)
#pragma unroll
        for (int e = 0; e < NEXP; e++)
            acc[e] += __shfl_down_sync(0xffffffffu, acc[e], off);

    if (lane == 0) {
        float mx = acc[0];
#pragma unroll
        for (int e = 1; e < NEXP; e++) mx = fmaxf(mx, acc[e]);
        float p[NEXP];
#pragma unroll
        for (int e = 0; e < NEXP; e++) p[e] = acc[e];

        int   sel[TOPK];
        float g[TOPK];
        float s = 0.f;
#pragma unroll
        for (int k = 0; k < TOPK; k++) {
            int best = 0; float bv = -INFINITY;
#pragma unroll
            for (int e = 0; e < NEXP; e++)
                if (p[e] > bv) { bv = p[e]; best = e; }   // first-index tie-break
            sel[k] = best;
            g[k]   = expf(bv - mx);
            s     += g[k];
            p[best] = -INFINITY;
        }
        float inv = 1.f / s;
#pragma unroll
        for (int k = 0; k < TOPK; k++) {
            int e   = sel[k];
            int pos = atomicAdd(&g_counts[e], 1);
            g_tok[e * CAP + pos]           = tok;
            g_slot_epos[tok * TOPK + k]    = e * CAP + pos;
            g_slot_gate[tok * TOPK + k]    = g[k] * inv;
        }
    }
}

// ---------------- grouped sparse GEMM (tf32 WMMA, 64x64x32 tiles) -----------
// PHASE 0: H1 = silu(gather(X) @ W1)   K=2048 N=4096
// PHASE 1: H2 = silu(H1 @ W2)          K=4096 N=4096
// PHASE 2: Y  = H2 @ W3                K=4096 N=2048
template<int PHASE>
__global__ void __launch_bounds__(128)
gemm_kernel(const float* __restrict__ x, const float* __restrict__ W) {
    constexpr int  K      = (PHASE == 0) ? HDIM : IDIM;
    constexpr int  N      = (PHASE == 2) ? HDIM : IDIM;
    constexpr bool GATHER = (PHASE == 0);
    constexpr bool SILU   = (PHASE < 2);
    constexpr int  LDA = 40;   // 32 + 8 pad
    constexpr int  LDB = 72;   // 64 + 8 pad

    const int tid     = threadIdx.x;
    const int e       = blockIdx.z;
    const int n_e     = g_counts[e];
    const int rowBase = blockIdx.y * 64;
    if (rowBase >= n_e) return;
    const int colBase = blockIdx.x * 64;

    __shared__ float smemBuf[64 * LDA + 32 * LDB];   // also reused as epilogue stage
    __shared__ int   srow[64];
    float* sA = smemBuf;
    float* sB = smemBuf + 64 * LDA;

    if (tid < 64) {
        int r  = rowBase + tid;
        int rr = (r < n_e) ? r : rowBase;            // clamp to a valid row
        srow[tid] = GATHER ? g_tok[e * CAP + rr] : rr;
    }
    __syncthreads();

    const float* A;
    float* C;
    if (PHASE == 0)      { A = x;                                 C = g_h1 + (size_t)e * CAP * IDIM; }
    else if (PHASE == 1) { A = g_h1 + (size_t)e * CAP * IDIM;     C = g_h2 + (size_t)e * CAP * IDIM; }
    else                 { A = g_h2 + (size_t)e * CAP * IDIM;     C = g_y  + (size_t)e * CAP * HDIM; }
    const float* B = W + (size_t)e * K * N;

    const int warpId = tid >> 5;
    const int wr = (warpId >> 1) * 32;
    const int wc = (warpId & 1)  * 32;

    wmma::fragment<wmma::accumulator, 16, 16, 8, float> acc[2][2];
#pragma unroll
    for (int i = 0; i < 2; i++)
#pragma unroll
        for (int j = 0; j < 2; j++) wmma::fill_fragment(acc[i][j], 0.f);

    const int atr = tid >> 3;          // 0..15
    const int atc = (tid & 7) * 4;     // 0..28
    const int btr = tid >> 4;          // 0..7
    const int btc = (tid & 15) * 4;    // 0..60

    for (int k0 = 0; k0 < K; k0 += 32) {
#pragma unroll
        for (int i = 0; i < 4; i++) {
            int m = atr + i * 16;
            float4 v = *(const float4*)(A + (size_t)srow[m] * K + (k0 + atc));
            *(float4*)(sA + m * LDA + atc) = v;
        }
#pragma unroll
        for (int p = 0; p < 4; p++) {
            int kk = btr + p * 8;
            float4 v = *(const float4*)(B + (size_t)(k0 + kk) * N + (colBase + btc));
            *(float4*)(sB + kk * LDB + btc) = v;
        }
        __syncthreads();

#pragma unroll
        for (int kk = 0; kk < 32; kk += 8) {
            wmma::fragment<wmma::matrix_a, 16, 16, 8, wmma::precision::tf32, wmma::row_major> af[2];
            wmma::fragment<wmma::matrix_b, 16, 16, 8, wmma::precision::tf32, wmma::row_major> bf[2];
#pragma unroll
            for (int i = 0; i < 2; i++) {
                wmma::load_matrix_sync(af[i], sA + (wr + i * 16) * LDA + kk, LDA);
#pragma unroll
                for (int t = 0; t < af[i].num_elements; t++)
                    af[i].x[t] = wmma::__float_to_tf32(af[i].x[t]);
            }
#pragma unroll
            for (int j = 0; j < 2; j++) {
                wmma::load_matrix_sync(bf[j], sB + kk * LDB + wc + j * 16, LDB);
#pragma unroll
                for (int t = 0; t < bf[j].num_elements; t++)
                    bf[j].x[t] = wmma::__float_to_tf32(bf[j].x[t]);
            }
#pragma unroll
            for (int i = 0; i < 2; i++)
#pragma unroll
                for (int j = 0; j < 2; j++)
                    wmma::mma_sync(acc[i][j], af[i], bf[j], acc[i][j]);
        }
        __syncthreads();
    }

    // epilogue: stage per-warp 32x32 in smem, apply SiLU, coalesced store
    float* stage = smemBuf + warpId * 1024;
#pragma unroll
    for (int i = 0; i < 2; i++)
#pragma unroll
        for (int j = 0; j < 2; j++)
            wmma::store_matrix_sync(stage + i * 16 * 32 + j * 16, acc[i][j], 32,
                                    wmma::mem_row_major);
    __syncwarp();

    const int lane = tid & 31;
#pragma unroll
    for (int r = 0; r < 32; r++) {
        int gr = rowBase + wr + r;
        if (gr < n_e) {
            float v = stage[r * 32 + lane];
            if (SILU) v = v / (1.f + expf(-v));
            C[(size_t)gr * N + colBase + wc + lane] = v;
        }
    }
}

// ---------------- deterministic combine -------------------------------------
__global__ void combine_kernel(float* __restrict__ out) {
    int idx   = blockIdx.x * blockDim.x + threadIdx.x;
    int total = T_TOK * (HDIM / 4);
    if (idx >= total) return;
    int t  = idx / (HDIM / 4);
    int h4 = (idx % (HDIM / 4)) * 4;

    float4 s = make_float4(0.f, 0.f, 0.f, 0.f);
#pragma unroll
    for (int k = 0; k < TOPK; k++) {
        int   ep = g_slot_epos[t * TOPK + k];
        float gk = g_slot_gate[t * TOPK + k];
        float4 y = *(const float4*)(g_y + (size_t)ep * HDIM + h4);
        s.x += gk * y.x; s.y += gk * y.y; s.z += gk * y.z; s.w += gk * y.w;
    }
    *(float4*)(out + (size_t)t * HDIM + h4) = s;
}

// ---------------- launch -----------------------------------------------------
extern "C" void kernel_launch(void* const* d_in, const int* in_sizes, int n_in,
                              void* d_out, int out_size) {
    const float* x  = (const float*)d_in[0];   // hidden_states [B,S,H]
    const float* rw = (const float*)d_in[1];   // router_w [H,E]
    const float* w1 = (const float*)d_in[2];   // [E,H,I]
    const float* w2 = (const float*)d_in[3];   // [E,I,I]
    const float* w3 = (const float*)d_in[4];   // [E,I,H]
    float* out = (float*)d_out;

    init_kernel<<<1, 32>>>();
    router_kernel<<<(T_TOK * 32) / 128, 128>>>(x, rw);

    dim3 blk(128);
    gemm_kernel<0><<<dim3(IDIM / 64, CAP / 64, NEXP), blk>>>(x, w1);
    gemm_kernel<1><<<dim3(IDIM / 64, CAP / 64, NEXP), blk>>>(x, w2);
    gemm_kernel<2><<<dim3(HDIM / 64, CAP / 64, NEXP), blk>>>(x, w3);

    combine_kernel<<<(T_TOK * (HDIM / 4) + 255) / 256, 256>>>(out);
}